// round 6
// baseline (speedup 1.0000x reference)
#include <cuda_runtime.h>

#define BATCH 65536
#define NBLK 512
#define TPB 128
#define NSETUP 64
typedef unsigned long long ull;

__device__ float g_Cpart[8][81 * 8];   // per-j-chunk partial C tensors
__device__ unsigned g_done;            // setup-completion counter (self-resetting)
__device__ unsigned g_pass;            // block-exit counter (self-resetting)

__device__ __forceinline__ float2 cmul(float2 a, float2 b) {
    return make_float2(a.x * b.x - a.y * b.y, a.x * b.y + a.y * b.x);
}
__device__ __forceinline__ void ffma2(ull& d, ull a, ull b) {
    asm("fma.rn.f32x2 %0, %1, %2, %0;" : "+l"(d) : "l"(a), "l"(b));
}
__device__ __forceinline__ ull mul2(ull a, ull b) {
    ull r;
    asm("mul.rn.f32x2 %0, %1, %2;" : "=l"(r) : "l"(a), "l"(b));
    return r;
}
__device__ __forceinline__ ull dup2(float p) {
    ull r;
    asm("mov.b64 %0, {%1, %2};" : "=l"(r) : "f"(p), "f"(p));
    return r;
}
__device__ __forceinline__ float2 shfl2(float2 v, int src) {
    float2 r;
    r.x = __shfl_sync(0xffffffffu, v.x, src);
    r.y = __shfl_sync(0xffffffffu, v.y, src);
    return r;
}

// swizzled smem index for M: row j (128 B), column XOR'd by j&15 -> conflict-free
#define SIDX(j, c) (((j) << 4) | ((c) ^ ((j) & 15)))

// ---------------------------------------------------------------------------
// ONE kernel. Blocks 0..63 = (wire i) x (j-chunk q) setup roles; all 512
// blocks then contract 128 samples each. All blocks co-resident (>=4/SM by
// launch_bounds; 512 <= 592 capacity) so the spin-wait cannot deadlock.
// ---------------------------------------------------------------------------
__global__ void __launch_bounds__(TPB, 4) fused_all(const float* __restrict__ x,
                                                    const float* __restrict__ params,
                                                    float* __restrict__ out) {
    __shared__ float2 Ms[4096];          // 32 KB swizzled M
    __shared__ float2 G[16][4];
    __shared__ float Csh[81];
    __shared__ __align__(16) float Cs[81 * 8];

    int t = threadIdx.x;                 // 0..127
    int ln = t & 31;
    int w = t >> 5;                      // warp 0..3
    int bid = blockIdx.x;

    // ================= setup role (blocks 0..63) =================
    if (bid < NSETUP) {
        int i = bid & 7;                 // output wire
        int q = bid >> 3;                // j chunk

        if (t < 16) {
            int layer = t >> 3, wi = t & 7;
            const float* p = params + layer * 24 + wi * 3;
            float cx, sx, cy, sy, cz, sz;
            __sincosf(0.5f * p[0], &sx, &cx);
            __sincosf(0.5f * p[1], &sy, &cy);
            __sincosf(0.5f * p[2], &sz, &cz);
            float2 a00 = make_float2( cy * cx,  sy * sx);
            float2 a01 = make_float2(-sy * cx, -cy * sx);
            float2 a10 = make_float2( sy * cx, -cy * sx);
            float2 a11 = make_float2( cy * cx, -sy * sx);
            float2 e0 = make_float2(cz, -sz), e1 = make_float2(cz, sz);
            G[t][0] = cmul(e0, a00);
            G[t][1] = cmul(e0, a01);
            G[t][2] = cmul(e1, a10);
            G[t][3] = cmul(e1, a11);
        }
        if (t < 81) Csh[t] = 0.f;
        __syncthreads();

        // ---- register sim: warp w owns columns 4w..4w+3; j = ln + 32r ----
        float2 st[4][8];
#pragma unroll
        for (int h = 0; h < 4; ++h) {
            int col = 4 * w + h;
#pragma unroll
            for (int r = 0; r < 8; ++r)
                st[h][r] = make_float2(
                    (r == (col >> 1) && ln == ((col & 1) << 4)) ? 1.f : 0.f, 0.f);
        }

#pragma unroll
        for (int layer = 0; layer < 2; ++layer) {
#pragma unroll
            for (int wi = 0; wi < 8; ++wi) {
                int g = layer * 8 + wi;
                float2 g00 = G[g][0], g01 = G[g][1], g10 = G[g][2], g11 = G[g][3];
                if (wi < 3) {
                    int rb = 1 << (2 - wi);
#pragma unroll
                    for (int h = 0; h < 4; ++h)
#pragma unroll
                        for (int r = 0; r < 8; ++r) {
                            if (r & rb) continue;
                            int r1 = r | rb;
                            float2 a0 = st[h][r], a1 = st[h][r1];
                            float2 n0, n1;
                            n0.x = g00.x * a0.x - g00.y * a0.y + g01.x * a1.x - g01.y * a1.y;
                            n0.y = g00.x * a0.y + g00.y * a0.x + g01.x * a1.y + g01.y * a1.x;
                            n1.x = g10.x * a0.x - g10.y * a0.y + g11.x * a1.x - g11.y * a1.y;
                            n1.y = g10.x * a0.y + g10.y * a0.x + g11.x * a1.y + g11.y * a1.x;
                            st[h][r] = n0; st[h][r1] = n1;
                        }
                } else {
                    int mk = 1 << (7 - wi);
                    bool hi = (ln & mk) != 0;
                    float2 ga = hi ? g11 : g00;
                    float2 gb = hi ? g10 : g01;
#pragma unroll
                    for (int h = 0; h < 4; ++h)
#pragma unroll
                        for (int r = 0; r < 8; ++r) {
                            float2 m = st[h][r];
                            float2 p;
                            p.x = __shfl_xor_sync(0xffffffffu, m.x, mk);
                            p.y = __shfl_xor_sync(0xffffffffu, m.y, mk);
                            float2 n;
                            n.x = ga.x * m.x - ga.y * m.y + gb.x * p.x - gb.y * p.y;
                            n.y = ga.x * m.y + ga.y * m.x + gb.x * p.y + gb.y * p.x;
                            st[h][r] = n;
                        }
                }
            }
            // CNOT chain: new[j] = old[j ^ (j>>1)]
            int baseLane = (ln ^ (ln >> 1)) & 31;
            float2 tmp[4][8];
#pragma unroll
            for (int h = 0; h < 4; ++h)
#pragma unroll
                for (int r = 0; r < 8; ++r) {
                    int sr = r ^ (r >> 1);
                    int srcLane = baseLane ^ ((r & 1) << 4);
                    tmp[h][r] = shfl2(st[h][sr], srcLane);
                }
#pragma unroll
            for (int h = 0; h < 4; ++h)
#pragma unroll
                for (int r = 0; r < 8; ++r) st[h][r] = tmp[h][r];
        }

        // write M to swizzled smem
#pragma unroll
        for (int h = 0; h < 4; ++h)
#pragma unroll
            for (int r = 0; r < 8; ++r) {
                int j = ln + 32 * r;
                Ms[SIDX(j, 4 * w + h)] = st[h][r];
            }
        __syncthreads();

        // ---- BC slice: wire i, j in [32q, 32q+32); 2 (k,l) pairs/thread ----
        int shift = 7 - i;
#pragma unroll
        for (int half = 0; half < 2; ++half) {
            int kl = t + 128 * half;
            int k = kl >> 4, l = kl & 15;
            float ar = 0.f, ai = 0.f;
#pragma unroll
            for (int jj = 0; jj < 32; ++jj) {
                int j = q * 32 + jj;
                float2 mk2 = Ms[SIDX(j, k)];
                float2 ml2 = Ms[SIDX(j, l)];
                float pr = mk2.x * ml2.x + mk2.y * ml2.y;
                float pi = mk2.x * ml2.y - mk2.y * ml2.x;
                float sg = ((j >> shift) & 1) ? -1.f : 1.f;
                ar = fmaf(sg, pr, ar);
                ai = fmaf(sg, pi, ai);
            }
            int d = (__popc(k) - __popc(l)) & 3;
            float val = (d == 0) ? ar : (d == 1) ? -ai : (d == 2) ? -ar : ai;
            int m = (((k >> 3) & 1) + ((l >> 3) & 1)) * 27 +
                    (((k >> 2) & 1) + ((l >> 2) & 1)) * 9 +
                    (((k >> 1) & 1) + ((l >> 1) & 1)) * 3 +
                    ((k & 1) + (l & 1));
            atomicAdd(&Csh[m], val);
        }
        __syncthreads();
        if (t < 81) g_Cpart[q][t * 8 + i] = Csh[t];
        __threadfence();                         // release partials
        __syncthreads();
        if (t == 0) atomicAdd(&g_done, 1);
    }

    // ================= contraction (all 512 blocks) =================
    int s = bid * TPB + t;                       // one sample per thread
    const float QP = 0.78539816339744831f;       // pi/4

    float4 xv = reinterpret_cast<const float4*>(x)[s];
    float c0, s_0, c1, s_1, c2, s_2, c3, s_3;
    __sincosf((xv.x + 1.f) * QP, &s_0, &c0);
    __sincosf((xv.y + 1.f) * QP, &s_1, &c1);
    __sincosf((xv.z + 1.f) * QP, &s_2, &c2);
    __sincosf((xv.w + 1.f) * QP, &s_3, &c3);
    float u0[3] = {c0 * c0, c0 * s_0, s_0 * s_0};
    float u1[3] = {c1 * c1, c1 * s_1, s_1 * s_1};
    float u2[3] = {c2 * c2, c2 * s_2, s_2 * s_2};
    float u3[3] = {c3 * c3, c3 * s_3, s_3 * s_3};
    ull u01d[9], u23d[9];
#pragma unroll
    for (int a = 0; a < 3; ++a)
#pragma unroll
        for (int c = 0; c < 3; ++c) {
            u01d[a * 3 + c] = dup2(u0[a] * u1[c]);
            u23d[a * 3 + c] = dup2(u2[a] * u3[c]);
        }

    // wait for all 64 setup blocks
    if (t == 0) {
        unsigned v;
        do {
            asm volatile("ld.acquire.gpu.global.u32 %0, [%1];"
                         : "=r"(v) : "l"(&g_done));
        } while (v < NSETUP);
    }
    __syncthreads();

    // stage C: sum the 8 chunk-partials (L2 loads, bypass L1)
    for (int idx = t; idx < 81 * 8; idx += TPB) {
        float sum = 0.f;
#pragma unroll
        for (int q = 0; q < 8; ++q) sum += __ldcg(&g_Cpart[q][idx]);
        Cs[idx] = sum;
    }
    __syncthreads();

    ull acc0 = 0ull, acc1 = 0ull, acc2 = 0ull, acc3 = 0ull;
#pragma unroll
    for (int a = 0; a < 9; ++a) {
#pragma unroll
        for (int c = 0; c < 9; ++c) {
            const ull* cp = reinterpret_cast<const ull*>(&Cs[(a * 9 + c) * 8]);
            ull pp = mul2(u01d[a], u23d[c]);
            ffma2(acc0, cp[0], pp);
            ffma2(acc1, cp[1], pp);
            ffma2(acc2, cp[2], pp);
            ffma2(acc3, cp[3], pp);
        }
    }

    float4* o = reinterpret_cast<float4*>(out + (size_t)s * 8);
    float2 p0 = *reinterpret_cast<float2*>(&acc0);
    float2 p1 = *reinterpret_cast<float2*>(&acc1);
    float2 p2 = *reinterpret_cast<float2*>(&acc2);
    float2 p3 = *reinterpret_cast<float2*>(&acc3);
    o[0] = make_float4(p0.x, p0.y, p1.x, p1.y);
    o[1] = make_float4(p2.x, p2.y, p3.x, p3.y);

    // self-resetting exit protocol: last block clears both counters
    if (t == 0) {
        unsigned prev = atomicAdd(&g_pass, 1);
        if (prev == NBLK - 1) {
            g_pass = 0;
            g_done = 0;
            __threadfence();
        }
    }
}

// ---------------------------------------------------------------------------
extern "C" void kernel_launch(void* const* d_in, const int* in_sizes, int n_in,
                              void* d_out, int out_size) {
    const float* x = (const float*)d_in[0];        // (65536, 4)
    const float* params = (const float*)d_in[1];   // (2, 8, 3)
    float* out = (float*)d_out;                    // (65536, 8)

    fused_all<<<NBLK, TPB>>>(x, params, out);
}

// round 7
// speedup vs baseline: 1.4047x; 1.4047x over previous
#include <cuda_runtime.h>

#define DIM 256
#define NCOL 16
#define BATCH 65536
typedef unsigned long long ull;

__device__ float g_Cpart[8][81 * 8];   // per-j-chunk partial C tensors

__device__ __forceinline__ float2 cmul(float2 a, float2 b) {
    return make_float2(a.x * b.x - a.y * b.y, a.x * b.y + a.y * b.x);
}
__device__ __forceinline__ void ffma2(ull& d, ull a, ull b) {
    asm("fma.rn.f32x2 %0, %1, %2, %0;" : "+l"(d) : "l"(a), "l"(b));
}
__device__ __forceinline__ ull mul2(ull a, ull b) {
    ull r;
    asm("mul.rn.f32x2 %0, %1, %2;" : "=l"(r) : "l"(a), "l"(b));
    return r;
}
__device__ __forceinline__ ull dup2(float p) {
    ull r;
    asm("mov.b64 %0, {%1, %2};" : "=l"(r) : "f"(p), "f"(p));
    return r;
}
__device__ __forceinline__ float2 shfl2(float2 v, int src) {
    float2 r;
    r.x = __shfl_sync(0xffffffffu, v.x, src);
    r.y = __shfl_sync(0xffffffffu, v.y, src);
    return r;
}

// swizzled smem index for M: row j (128 B), column XOR'd by j&15 -> conflict-free
#define SIDX(j, c) (((j) << 4) | ((c) ^ ((j) & 15)))

// ---------------------------------------------------------------------------
// K1 (fused setup): 64 blocks = (8 wires i) x (8 j-chunks q), 256 threads.
// Phase A: all-register sim of the 16 relevant columns (8 warps x 2 cols).
// Phase B: swizzled smem M; BC slice for (i, q) -> g_Cpart.
// ---------------------------------------------------------------------------
__global__ void __launch_bounds__(256) fused_setup(const float* __restrict__ params) {
    __shared__ float2 Ms[DIM * NCOL];    // 32 KB, swizzled
    __shared__ float2 G[16][4];
    __shared__ float Csh[81];

    int t = threadIdx.x;
    int ln = t & 31;
    int w = t >> 5;                      // warp id = column pair
    int i = blockIdx.x & 7;              // output wire
    int q = blockIdx.x >> 3;             // j chunk

    if (t < 16) {
        int layer = t >> 3, wi = t & 7;
        const float* p = params + layer * 24 + wi * 3;
        float cx, sx, cy, sy, cz, sz;
        __sincosf(0.5f * p[0], &sx, &cx);
        __sincosf(0.5f * p[1], &sy, &cy);
        __sincosf(0.5f * p[2], &sz, &cz);
        float2 a00 = make_float2( cy * cx,  sy * sx);
        float2 a01 = make_float2(-sy * cx, -cy * sx);
        float2 a10 = make_float2( sy * cx, -cy * sx);
        float2 a11 = make_float2( cy * cx, -sy * sx);
        float2 e0 = make_float2(cz, -sz), e1 = make_float2(cz, sz);
        G[t][0] = cmul(e0, a00);
        G[t][1] = cmul(e0, a01);
        G[t][2] = cmul(e1, a10);
        G[t][3] = cmul(e1, a11);
    }
    if (t < 81) Csh[t] = 0.f;
    __syncthreads();

    // -------- Phase A: register sim (warp w owns columns 2w, 2w+1) --------
    float2 st[2][8];
#pragma unroll
    for (int h = 0; h < 2; ++h)
#pragma unroll
        for (int r = 0; r < 8; ++r)
            st[h][r] = make_float2((r == w && ln == (h << 4)) ? 1.f : 0.f, 0.f);

#pragma unroll
    for (int layer = 0; layer < 2; ++layer) {
#pragma unroll
        for (int wi = 0; wi < 8; ++wi) {
            int g = layer * 8 + wi;
            float2 g00 = G[g][0], g01 = G[g][1], g10 = G[g][2], g11 = G[g][3];
            if (wi < 3) {
                int rb = 1 << (2 - wi);
#pragma unroll
                for (int h = 0; h < 2; ++h)
#pragma unroll
                    for (int r = 0; r < 8; ++r) {
                        if (r & rb) continue;
                        int r1 = r | rb;
                        float2 a0 = st[h][r], a1 = st[h][r1];
                        float2 n0, n1;
                        n0.x = g00.x * a0.x - g00.y * a0.y + g01.x * a1.x - g01.y * a1.y;
                        n0.y = g00.x * a0.y + g00.y * a0.x + g01.x * a1.y + g01.y * a1.x;
                        n1.x = g10.x * a0.x - g10.y * a0.y + g11.x * a1.x - g11.y * a1.y;
                        n1.y = g10.x * a0.y + g10.y * a0.x + g11.x * a1.y + g11.y * a1.x;
                        st[h][r] = n0; st[h][r1] = n1;
                    }
            } else {
                int mk = 1 << (7 - wi);
                bool hi = (ln & mk) != 0;
                float2 ga = hi ? g11 : g00;
                float2 gb = hi ? g10 : g01;
#pragma unroll
                for (int h = 0; h < 2; ++h)
#pragma unroll
                    for (int r = 0; r < 8; ++r) {
                        float2 m = st[h][r];
                        float2 p;
                        p.x = __shfl_xor_sync(0xffffffffu, m.x, mk);
                        p.y = __shfl_xor_sync(0xffffffffu, m.y, mk);
                        float2 n;
                        n.x = ga.x * m.x - ga.y * m.y + gb.x * p.x - gb.y * p.y;
                        n.y = ga.x * m.y + ga.y * m.x + gb.x * p.y + gb.y * p.x;
                        st[h][r] = n;
                    }
            }
        }
        // CNOT chain: new[j] = old[j ^ (j>>1)]
        int baseLane = (ln ^ (ln >> 1)) & 31;
        float2 tmp[2][8];
#pragma unroll
        for (int h = 0; h < 2; ++h)
#pragma unroll
            for (int r = 0; r < 8; ++r) {
                int sr = r ^ (r >> 1);
                int srcLane = baseLane ^ ((r & 1) << 4);
                tmp[h][r] = shfl2(st[h][sr], srcLane);
            }
#pragma unroll
        for (int h = 0; h < 2; ++h)
#pragma unroll
            for (int r = 0; r < 8; ++r) st[h][r] = tmp[h][r];
    }

#pragma unroll
    for (int h = 0; h < 2; ++h)
#pragma unroll
        for (int r = 0; r < 8; ++r) {
            int j = ln + 32 * r;
            Ms[SIDX(j, 2 * w + h)] = st[h][r];
        }
    __syncthreads();

    // -------- Phase B: BC slice (wire i, j in [32q, 32q+32)) --------
    int k = t >> 4, l = t & 15;
    int shift = 7 - i;
    float ar = 0.f, ai = 0.f;
#pragma unroll
    for (int jj = 0; jj < 32; ++jj) {
        int j = q * 32 + jj;
        float2 mk2 = Ms[SIDX(j, k)];
        float2 ml2 = Ms[SIDX(j, l)];
        float pr = mk2.x * ml2.x + mk2.y * ml2.y;
        float pi = mk2.x * ml2.y - mk2.y * ml2.x;
        float sg = ((j >> shift) & 1) ? -1.f : 1.f;
        ar = fmaf(sg, pr, ar);
        ai = fmaf(sg, pi, ai);
    }
    int d = (__popc(k) - __popc(l)) & 3;
    float val = (d == 0) ? ar : (d == 1) ? -ai : (d == 2) ? -ar : ai;
    int m = (((k >> 3) & 1) + ((l >> 3) & 1)) * 27 +
            (((k >> 2) & 1) + ((l >> 2) & 1)) * 9 +
            (((k >> 1) & 1) + ((l >> 1) & 1)) * 3 +
            ((k & 1) + (l & 1));
    atomicAdd(&Csh[m], val);
    __syncthreads();
    if (t < 81) g_Cpart[q][t * 8 + i] = Csh[t];
}

// ---------------------------------------------------------------------------
// K2: 1 sample/thread, 256 blocks x 256 threads (2048 warps for latency
// hiding). f32x2 packed FFMA; C staged in smem from the 8 chunk-partials.
// ---------------------------------------------------------------------------
__global__ void __launch_bounds__(256) qmain(const float* __restrict__ x,
                                             float* __restrict__ out) {
    __shared__ __align__(16) float Cs[81 * 8];
    int t = threadIdx.x;
    for (int idx = t; idx < 81 * 8; idx += 256) {
        float sum = 0.f;
#pragma unroll
        for (int q = 0; q < 8; ++q) sum += __ldcg(&g_Cpart[q][idx]);
        Cs[idx] = sum;
    }
    __syncthreads();

    int s = blockIdx.x * 256 + t;
    const float QP = 0.78539816339744831f;  // pi/4

    float4 xv = reinterpret_cast<const float4*>(x)[s];
    float c0, s_0, c1, s_1, c2, s_2, c3, s_3;
    __sincosf((xv.x + 1.f) * QP, &s_0, &c0);
    __sincosf((xv.y + 1.f) * QP, &s_1, &c1);
    __sincosf((xv.z + 1.f) * QP, &s_2, &c2);
    __sincosf((xv.w + 1.f) * QP, &s_3, &c3);
    float u0[3] = {c0 * c0, c0 * s_0, s_0 * s_0};
    float u1[3] = {c1 * c1, c1 * s_1, s_1 * s_1};
    float u2[3] = {c2 * c2, c2 * s_2, s_2 * s_2};
    float u3[3] = {c3 * c3, c3 * s_3, s_3 * s_3};
    ull u01d[9], u23d[9];
#pragma unroll
    for (int a = 0; a < 3; ++a)
#pragma unroll
        for (int c = 0; c < 3; ++c) {
            u01d[a * 3 + c] = dup2(u0[a] * u1[c]);
            u23d[a * 3 + c] = dup2(u2[a] * u3[c]);
        }

    ull acc0 = 0ull, acc1 = 0ull, acc2 = 0ull, acc3 = 0ull;
#pragma unroll
    for (int a = 0; a < 9; ++a) {
#pragma unroll
        for (int c = 0; c < 9; ++c) {
            const ull* cp = reinterpret_cast<const ull*>(&Cs[(a * 9 + c) * 8]);
            ull pp = mul2(u01d[a], u23d[c]);
            ffma2(acc0, cp[0], pp);
            ffma2(acc1, cp[1], pp);
            ffma2(acc2, cp[2], pp);
            ffma2(acc3, cp[3], pp);
        }
    }

    float4* o = reinterpret_cast<float4*>(out + (size_t)s * 8);
    float2 p0 = *reinterpret_cast<float2*>(&acc0);
    float2 p1 = *reinterpret_cast<float2*>(&acc1);
    float2 p2 = *reinterpret_cast<float2*>(&acc2);
    float2 p3 = *reinterpret_cast<float2*>(&acc3);
    o[0] = make_float4(p0.x, p0.y, p1.x, p1.y);
    o[1] = make_float4(p2.x, p2.y, p3.x, p3.y);
}

// ---------------------------------------------------------------------------
extern "C" void kernel_launch(void* const* d_in, const int* in_sizes, int n_in,
                              void* d_out, int out_size) {
    const float* x = (const float*)d_in[0];        // (65536, 4)
    const float* params = (const float*)d_in[1];   // (2, 8, 3)
    float* out = (float*)d_out;                    // (65536, 8)

    fused_setup<<<64, 256>>>(params);
    qmain<<<BATCH / 256, 256>>>(x, out);
}